// round 16
// baseline (speedup 1.0000x reference)
#include <cuda_runtime.h>
#include <math.h>

#define B_    32
#define C_    2048
#define T_    16
#define S_    49
#define H_    512
#define HID_  1024
#define OUT_  101
#define M_    2048      // gate rows (= 4*H) / layer0 rows
#define KTOT_ 2560      // C + H

// ---------------- device scratch ----------------
__device__ __align__(16) float g_xt[T_ * B_ * S_ * C_];  // [t][b][s][c]
__device__ __align__(16) float g_Wt[KTOT_ * M_];         // gates W^T [k][row]
__device__ __align__(16) float g_Wt0[C_ * M_];           // layer0 W^T [k][row]
__device__ __align__(16) float g_A[KTOT_ * B_];          // [k][b]
__device__ __align__(16) float g_A0[C_ * B_];            // pooled^T [k][b]
__device__ __align__(16) float g_gates[B_ * M_];         // gates accum [b][row] (zeroed by k_cell)
__device__ __align__(16) float g_hid0[B_ * M_];          // layer0 accum [b][row] (zeroed by k_tw)
__device__ __align__(16) float g_hidh[B_ * HID_];
__device__ __align__(16) float g_hidc[B_ * HID_];
__device__ __align__(16) float g_h0[B_ * H_];
__device__ __align__(16) float g_c[B_ * H_];
__device__ __align__(16) float g_hsum[B_ * H_];
__device__ __align__(16) float g_alpha[B_ * 64];

__device__ __forceinline__ float warp_sum(float v) {
    #pragma unroll
    for (int o = 16; o; o >>= 1) v += __shfl_xor_sync(0xFFFFFFFFu, v, o);
    return v;
}
__device__ __forceinline__ float sigmoidf_(float x) {
    return 1.0f / (1.0f + expf(-x));
}

// ------- merged weight transposes (+ zero g_A0 and g_hid0) -----------------
__global__ __launch_bounds__(256) void k_tw(
    const float* __restrict__ wih, const float* __restrict__ whh,
    const float* __restrict__ w0h, const float* __restrict__ w0c) {
    if (blockIdx.z == 0 && blockIdx.y == 0 && blockIdx.x < 8) {
        int base = blockIdx.x * 256 + threadIdx.x;
        #pragma unroll
        for (int k = 0; k < 32; k++) g_A0[base + k * 2048] = 0.f;
        #pragma unroll
        for (int k = 0; k < 32; k++) g_hid0[base + k * 2048] = 0.f;
    }
    if (blockIdx.z == 1 && blockIdx.x >= 64) return;
    __shared__ float s[32][33];
    int k0 = blockIdx.x * 32;
    int r0 = blockIdx.y * 32;
    int tx = threadIdx.x & 31, ty = threadIdx.x >> 5;
    if (blockIdx.z == 0) {
        #pragma unroll
        for (int i = 0; i < 4; i++) {
            int row = r0 + ty + 8 * i, k = k0 + tx;
            s[ty + 8 * i][tx] = (k < C_) ? wih[(size_t)row * C_ + k]
                                         : whh[(size_t)row * H_ + (k - C_)];
        }
        __syncthreads();
        #pragma unroll
        for (int i = 0; i < 4; i++) {
            int k = k0 + ty + 8 * i;
            g_Wt[(size_t)k * M_ + r0 + tx] = s[tx][ty + 8 * i];
        }
    } else {
        #pragma unroll
        for (int i = 0; i < 4; i++) {
            int row = r0 + ty + 8 * i, k = k0 + tx;
            s[ty + 8 * i][tx] = (row < HID_) ? w0h[(size_t)row * C_ + k]
                                             : w0c[(size_t)(row - HID_) * C_ + k];
        }
        __syncthreads();
        #pragma unroll
        for (int i = 0; i < 4; i++) {
            int k = k0 + ty + 8 * i;
            g_Wt0[(size_t)k * M_ + r0 + tx] = s[tx][ty + 8 * i];
        }
    }
}

// ------ x transpose to [t][b][s][c] + fused pooling into g_A0[k][b] --------
__global__ __launch_bounds__(256) void k_xt(const float* __restrict__ x) {
    __shared__ float sm[64][51];
    int c0 = blockIdx.x * 64;
    int t  = blockIdx.y;
    int b  = blockIdx.z;
    int w = threadIdx.x >> 5, lane = threadIdx.x & 31;
    #pragma unroll
    for (int rr = 0; rr < 8; rr++) {
        int cc = w * 8 + rr;
        int c  = c0 + cc;
        const float* src = x + (((size_t)(b * C_ + c) * T_) + t) * S_;
        float v1 = __ldcs(src + lane);
        float v2 = (lane < S_ - 32) ? __ldcs(src + 32 + lane) : 0.f;
        sm[cc][lane] = v1;
        if (lane < S_ - 32) sm[cc][32 + lane] = v2;
        float s = warp_sum(v1 + v2);
        if (lane == 0) atomicAdd(&g_A0[(size_t)c * B_ + b], s * (1.0f / 784.0f));
    }
    __syncthreads();
    size_t base = ((size_t)(t * B_ + b) * S_) * C_ + c0;
    for (int idx = threadIdx.x; idx < S_ * 16; idx += 256) {
        int s = idx >> 4, c4 = (idx & 15) * 4;
        float4 v = make_float4(sm[c4][s], sm[c4 + 1][s], sm[c4 + 2][s], sm[c4 + 3][s]);
        __stcs((float4*)(g_xt + base + (size_t)s * C_ + c4), v);
    }
}

// ------- split-K GEMM, pipelined W prefetch, atomic epilogue ---------------
// grid 256 = 8 tiles x 32 splits. SEL=0: layer0 (KC=64); SEL=1: gates (KC=80)
template<int SEL>
__global__ __launch_bounds__(256) void k_gemm() {
    constexpr int KC  = SEL ? 80 : 64;
    constexpr int NCH = KC / 4;
    const float* __restrict__ Wt = SEL ? g_Wt : g_Wt0;
    const float* __restrict__ A  = SEL ? g_A  : g_A0;
    float* __restrict__ OUTP     = SEL ? g_gates : g_hid0;
    __shared__ float sA[80 * 32];
    int rt = blockIdx.x & 7;
    int ks = blockIdx.x >> 3;
    int k0 = ks * KC;
    for (int i = threadIdx.x; i < (KC * 32) / 4; i += 256)
        ((float4*)sA)[i] = ((const float4*)(A + (size_t)k0 * 32))[i];
    __syncthreads();

    int w = threadIdx.x >> 5, lane = threadIdx.x & 31;
    int r0 = rt * 256 + w * 32 + (lane >> 2) * 4;
    int b0 = (lane & 3) * 8;

    float acc[4][8];
    #pragma unroll
    for (int i = 0; i < 4; i++)
        #pragma unroll
        for (int j = 0; j < 8; j++) acc[i][j] = 0.f;

    const float* wp = Wt + (size_t)k0 * M_ + r0;
    const float* ap = sA + b0;

    float4 wb0[4], wb1[4];
    #pragma unroll
    for (int p = 0; p < 4; p++)
        wb0[p] = *(const float4*)(wp + (size_t)p * M_);

    #define FMA_BLOCK(WV, KK) do {                                           \
        float4 av0 = *(const float4*)(ap + (KK) * 32);                        \
        float4 av1 = *(const float4*)(ap + (KK) * 32 + 4);                    \
        float wf[4] = {(WV).x, (WV).y, (WV).z, (WV).w};                       \
        float af[8] = {av0.x, av0.y, av0.z, av0.w, av1.x, av1.y, av1.z, av1.w};\
        _Pragma("unroll")                                                     \
        for (int i = 0; i < 4; i++)                                           \
            _Pragma("unroll")                                                 \
            for (int j = 0; j < 8; j++)                                       \
                acc[i][j] = fmaf(wf[i], af[j], acc[i][j]);                    \
    } while (0)

    for (int ch = 0; ch < NCH; ch += 2) {
        if (ch + 1 < NCH) {
            const float* wn = wp + (size_t)(ch + 1) * 4 * M_;
            #pragma unroll
            for (int p = 0; p < 4; p++)
                wb1[p] = *(const float4*)(wn + (size_t)p * M_);
        }
        #pragma unroll
        for (int p = 0; p < 4; p++) FMA_BLOCK(wb0[p], ch * 4 + p);
        if (ch + 2 < NCH) {
            const float* wn = wp + (size_t)(ch + 2) * 4 * M_;
            #pragma unroll
            for (int p = 0; p < 4; p++)
                wb0[p] = *(const float4*)(wn + (size_t)p * M_);
        }
        if (ch + 1 < NCH) {
            #pragma unroll
            for (int p = 0; p < 4; p++) FMA_BLOCK(wb1[p], (ch + 1) * 4 + p);
        }
    }
    #undef FMA_BLOCK

    #pragma unroll
    for (int j = 0; j < 8; j++) {
        float* dst = OUTP + (size_t)(b0 + j) * M_ + r0;
        atomicAdd(dst + 0, acc[0][j]);
        atomicAdd(dst + 1, acc[1][j]);
        atomicAdd(dst + 2, acc[2][j]);
        atomicAdd(dst + 3, acc[3][j]);
    }
}

// ---------------- layer0 bias add (g_hid0 -> hidh/hidc) --------------------
__global__ __launch_bounds__(256) void k_bias0(
    const float* __restrict__ b_h, const float* __restrict__ b_c) {
    int idx4 = blockIdx.x * 256 + threadIdx.x;    // 0 .. 16383 (float4 units)
    int b  = idx4 >> 9;
    int r4 = (idx4 & 511) * 4;
    float4 v = *(const float4*)&g_hid0[(size_t)b * M_ + r4];
    if (r4 < HID_) {
        float4 bb = *(const float4*)&b_h[r4];
        v.x += bb.x; v.y += bb.y; v.z += bb.z; v.w += bb.w;
        *(float4*)&g_hidh[b * HID_ + r4] = v;
    } else {
        float4 bb = *(const float4*)&b_c[r4 - HID_];
        v.x += bb.x; v.y += bb.y; v.z += bb.z; v.w += bb.w;
        *(float4*)&g_hidc[b * HID_ + (r4 - HID_)] = v;
    }
}

// ---------------- layer1: 4 outputs per warp --------------------------------
__global__ __launch_bounds__(256) void k_layer1(
    const float* __restrict__ w_h, const float* __restrict__ b_h,
    const float* __restrict__ w_c, const float* __restrict__ b_c) {
    int gw   = (blockIdx.x * 256 + threadIdx.x) >> 5;
    int lane = threadIdx.x & 31;
    int path = gw >> 12;
    int r    = gw & 4095;
    int b    = r >> 7;
    int j0   = (r & 127) * 4;
    const float* w   = path ? w_c : w_h;
    const float* src = path ? g_hidc : g_hidh;
    const float4* sp = (const float4*)(src + b * HID_);
    const float4* w0 = (const float4*)(w + (size_t)(j0)     * HID_);
    const float4* w1 = (const float4*)(w + (size_t)(j0 + 1) * HID_);
    const float4* w2 = (const float4*)(w + (size_t)(j0 + 2) * HID_);
    const float4* w3 = (const float4*)(w + (size_t)(j0 + 3) * HID_);
    float a0 = 0.f, a1 = 0.f, a2 = 0.f, a3 = 0.f;
    #pragma unroll 2
    for (int i = lane; i < HID_ / 4; i += 32) {
        float4 s4 = sp[i];
        float4 v;
        v = w0[i]; a0 += s4.x * v.x + s4.y * v.y + s4.z * v.z + s4.w * v.w;
        v = w1[i]; a1 += s4.x * v.x + s4.y * v.y + s4.z * v.z + s4.w * v.w;
        v = w2[i]; a2 += s4.x * v.x + s4.y * v.y + s4.z * v.z + s4.w * v.w;
        v = w3[i]; a3 += s4.x * v.x + s4.y * v.y + s4.z * v.z + s4.w * v.w;
    }
    a0 = warp_sum(a0); a1 = warp_sum(a1); a2 = warp_sum(a2); a3 = warp_sum(a3);
    if (lane == 0) {
        float o[4] = {a0, a1, a2, a3};
        #pragma unroll
        for (int m = 0; m < 4; m++) {
            int j = j0 + m;
            float v = o[m] + (path ? b_c[j] : b_h[j]);
            if (path == 0) {
                g_h0[b * H_ + j] = v;
                g_A[(size_t)(C_ + j) * B_ + b] = v;
            } else {
                g_c[b * H_ + j] = v;
            }
        }
    }
}

// ---------------- initial alpha from h0 ------------------------------------
__global__ __launch_bounds__(256) void k_alpha_init(
    const float* __restrict__ att_w, float* __restrict__ alpha_out) {
    int b = blockIdx.x;
    __shared__ float sh_h[H_];
    __shared__ float sh_e[56];
    int tid = threadIdx.x, warp = tid >> 5, lane = tid & 31;
    for (int i = tid; i < H_; i += 256) sh_h[i] = g_h0[b * H_ + i];
    __syncthreads();
    for (int s = warp; s < S_; s += 8) {
        float acc = 0.f;
        #pragma unroll
        for (int i = 0; i < 16; i++)
            acc += sh_h[lane + 32 * i] * __ldg(att_w + (size_t)s * H_ + lane + 32 * i);
        acc = warp_sum(acc);
        if (lane == 0) sh_e[s] = acc;
    }
    __syncthreads();
    if (warp == 0) {
        float e1 = sh_e[lane];
        float e2 = (lane < 17) ? sh_e[lane + 32] : -1e30f;
        float m = fmaxf(e1, e2);
        #pragma unroll
        for (int o = 16; o; o >>= 1) m = fmaxf(m, __shfl_xor_sync(0xFFFFFFFFu, m, o));
        float p1 = expf(e1 - m);
        float p2 = (lane < 17) ? expf(e2 - m) : 0.f;
        float sum = warp_sum(p1 + p2);
        float inv = 1.0f / sum;
        p1 *= inv; p2 *= inv;
        g_alpha[b * 64 + lane] = p1;
        alpha_out[((size_t)b * T_) * S_ + lane] = p1;
        if (lane < 17) {
            g_alpha[b * 64 + 32 + lane] = p2;
            alpha_out[((size_t)b * T_) * S_ + 32 + lane] = p2;
        }
    }
}

// ---------------- per step: context from g_xt (coalesced, float2) ----------
__global__ __launch_bounds__(256) void k_ctx(int t) {
    int b = blockIdx.x >> 2;
    int q = blockIdx.x & 3;
    __shared__ float sal[S_];
    if (threadIdx.x < S_) sal[threadIdx.x] = g_alpha[b * 64 + threadIdx.x];
    __syncthreads();
    int c = q * 512 + threadIdx.x * 2;
    const float* base = g_xt + ((size_t)(t * B_ + b) * S_) * C_ + c;
    float ax = 0.f, ay = 0.f;
    #pragma unroll 7
    for (int s = 0; s < S_; s++) {
        float2 v = __ldcs((const float2*)(base + (size_t)s * C_));
        float a = sal[s];
        ax = fmaf(a, v.x, ax);
        ay = fmaf(a, v.y, ay);
    }
    g_A[(size_t)c * B_ + b]       = ax;
    g_A[(size_t)(c + 1) * B_ + b] = ay;
}

// ------- per step: read gates + LSTM cell + re-zero + next alpha ------------
__global__ __launch_bounds__(512) void k_cell(
    const float* __restrict__ b_ih, const float* __restrict__ b_hh,
    const float* __restrict__ att_w, float* __restrict__ alpha_out, int t) {
    int b = blockIdx.x;
    int j = threadIdx.x;
    float* gp = g_gates + (size_t)b * M_;

    float gi = gp[j]        + b_ih[j]        + b_hh[j];
    float gf = gp[512 + j]  + b_ih[512 + j]  + b_hh[512 + j];
    float gg = gp[1024 + j] + b_ih[1024 + j] + b_hh[1024 + j];
    float go = gp[1536 + j] + b_ih[1536 + j] + b_hh[1536 + j];

    // re-zero for next step's atomic accumulation (same thread, same addrs)
    gp[j] = 0.f; gp[512 + j] = 0.f; gp[1024 + j] = 0.f; gp[1536 + j] = 0.f;

    float iv = sigmoidf_(gi);
    float fv = sigmoidf_(gf);
    float gv = tanhf(gg);
    float ov = sigmoidf_(go);
    int idx = b * H_ + j;
    float cn = fv * g_c[idx] + iv * gv;
    g_c[idx] = cn;
    float hn = ov * tanhf(cn);
    g_A[(size_t)(C_ + j) * B_ + b] = hn;
    g_hsum[idx] = (t == 0) ? hn : (g_hsum[idx] + hn);

    __shared__ float sh_h[H_];
    __shared__ float sh_e[56];
    sh_h[j] = hn;
    __syncthreads();

    if (t < T_ - 1) {
        int warp = j >> 5, lane = j & 31;
        for (int s = warp; s < S_; s += 16) {
            float acc = 0.f;
            #pragma unroll
            for (int i = 0; i < 16; i++)
                acc += sh_h[lane + 32 * i] * __ldg(att_w + (size_t)s * H_ + lane + 32 * i);
            acc = warp_sum(acc);
            if (lane == 0) sh_e[s] = acc;
        }
        __syncthreads();
        if (warp == 0) {
            float e1 = sh_e[lane];
            float e2 = (lane < 17) ? sh_e[lane + 32] : -1e30f;
            float m = fmaxf(e1, e2);
            #pragma unroll
            for (int o = 16; o; o >>= 1) m = fmaxf(m, __shfl_xor_sync(0xFFFFFFFFu, m, o));
            float p1 = expf(e1 - m);
            float p2 = (lane < 17) ? expf(e2 - m) : 0.f;
            float sum = warp_sum(p1 + p2);
            float inv = 1.0f / sum;
            p1 *= inv; p2 *= inv;
            g_alpha[b * 64 + lane] = p1;
            alpha_out[((size_t)b * T_ + (t + 1)) * S_ + lane] = p1;
            if (lane < 17) {
                g_alpha[b * 64 + 32 + lane] = p2;
                alpha_out[((size_t)b * T_ + (t + 1)) * S_ + 32 + lane] = p2;
            }
        }
    }
}

// ---------------- final output GEMV ----------------------------------------
__global__ __launch_bounds__(256) void k_final(
    const float* __restrict__ fc_out_w, const float* __restrict__ fc_out_b,
    float* __restrict__ out) {
    int gwid = (blockIdx.x * blockDim.x + threadIdx.x) >> 5;
    int lane = threadIdx.x & 31;
    if (gwid >= B_ * OUT_) return;
    int b = gwid / OUT_;
    int o = gwid % OUT_;
    const float4* wp = (const float4*)(fc_out_w + (size_t)o * H_);
    const float4* hp = (const float4*)(g_hsum + b * H_);
    float acc = 0.f;
    #pragma unroll 4
    for (int i = lane; i < H_ / 4; i += 32) {
        float4 a = hp[i], w = wp[i];
        acc += a.x * w.x + a.y * w.y + a.z * w.z + a.w * w.w;
    }
    acc = warp_sum(acc);
    if (lane == 0) out[gwid] = acc * (1.0f / (float)T_) + fc_out_b[o];
}

// ---------------- launch ----------------------------------------------------
extern "C" void kernel_launch(void* const* d_in, const int* in_sizes, int n_in,
                              void* d_out, int out_size) {
    const float* input_x   = (const float*)d_in[0];
    const float* att_hw_w  = (const float*)d_in[1];
    const float* fc_h0_0_w = (const float*)d_in[2];
    const float* fc_h0_0_b = (const float*)d_in[3];
    const float* fc_h0_1_w = (const float*)d_in[4];
    const float* fc_h0_1_b = (const float*)d_in[5];
    const float* fc_c0_0_w = (const float*)d_in[6];
    const float* fc_c0_0_b = (const float*)d_in[7];
    const float* fc_c0_1_w = (const float*)d_in[8];
    const float* fc_c0_1_b = (const float*)d_in[9];
    const float* w_ih      = (const float*)d_in[10];
    const float* b_ih      = (const float*)d_in[11];
    const float* w_hh      = (const float*)d_in[12];
    const float* b_hh      = (const float*)d_in[13];
    const float* fc_out_w  = (const float*)d_in[14];
    const float* fc_out_b  = (const float*)d_in[15];

    float* out       = (float*)d_out;
    float* alpha_out = out + B_ * OUT_;

    k_tw<<<dim3(KTOT_ / 32, M_ / 32, 2), 256>>>(w_ih, w_hh, fc_h0_0_w, fc_c0_0_w);
    k_xt<<<dim3(C_ / 64, T_, B_), 256>>>(input_x);      // transpose + fused pooling
    k_gemm<0><<<256, 256>>>();                          // layer0 GEMM (atomic out)
    k_bias0<<<64, 256>>>(fc_h0_0_b, fc_c0_0_b);
    k_layer1<<<1024, 256>>>(fc_h0_1_w, fc_h0_1_b, fc_c0_1_w, fc_c0_1_b);
    k_alpha_init<<<B_, 256>>>(att_hw_w, alpha_out);

    for (int t = 0; t < T_; t++) {
        k_ctx<<<B_ * 4, 256>>>(t);
        k_gemm<1><<<256, 256>>>();                      // gates GEMM (atomic out)
        k_cell<<<B_, 512>>>(b_ih, b_hh, att_hw_w, alpha_out, t);
    }

    k_final<<<(B_ * OUT_ + 7) / 8, 256>>>(fc_out_w, fc_out_b, out);
}

// round 17
// speedup vs baseline: 1.0691x; 1.0691x over previous
#include <cuda_runtime.h>
#include <math.h>

#define B_    32
#define C_    2048
#define T_    16
#define S_    49
#define H_    512
#define HID_  1024
#define OUT_  101
#define M_    2048      // gate rows (= 4*H) / layer0 rows
#define KTOT_ 2560      // C + H

// ---------------- device scratch ----------------
__device__ __align__(16) float g_xt[T_ * B_ * S_ * C_];  // [t][b][s][c]
__device__ __align__(16) float g_Wt[KTOT_ * M_];         // gates W^T [k][row]
__device__ __align__(16) float g_Wt0[C_ * M_];           // layer0 W^T [k][row]
__device__ __align__(16) float g_A[KTOT_ * B_];          // [k][b]
__device__ __align__(16) float g_A0[C_ * B_];            // pooled^T [k][b]
__device__ __align__(16) float g_part[32 * B_ * M_];     // split-K partials (8MB)
__device__ __align__(16) float g_hidh[B_ * HID_];
__device__ __align__(16) float g_hidc[B_ * HID_];
__device__ __align__(16) float g_h0[B_ * H_];
__device__ __align__(16) float g_c[B_ * H_];
__device__ __align__(16) float g_hsum[B_ * H_];
__device__ __align__(16) float g_alpha[B_ * 64];

__device__ __forceinline__ float warp_sum(float v) {
    #pragma unroll
    for (int o = 16; o; o >>= 1) v += __shfl_xor_sync(0xFFFFFFFFu, v, o);
    return v;
}
__device__ __forceinline__ float sigmoidf_(float x) {
    return 1.0f / (1.0f + expf(-x));
}

// ---------------- merged weight transposes (+ zero ALL of g_A0) ------------
__global__ __launch_bounds__(256) void k_tw(
    const float* __restrict__ wih, const float* __restrict__ whh,
    const float* __restrict__ w0h, const float* __restrict__ w0c) {
    if (blockIdx.z == 0 && blockIdx.y == 0 && blockIdx.x < 8) {
        int base = blockIdx.x * 256 + threadIdx.x;
        #pragma unroll
        for (int k = 0; k < 32; k++) g_A0[base + k * 2048] = 0.f;
    }
    if (blockIdx.z == 1 && blockIdx.x >= 64) return;
    __shared__ float s[32][33];
    int k0 = blockIdx.x * 32;
    int r0 = blockIdx.y * 32;
    int tx = threadIdx.x & 31, ty = threadIdx.x >> 5;
    if (blockIdx.z == 0) {
        #pragma unroll
        for (int i = 0; i < 4; i++) {
            int row = r0 + ty + 8 * i, k = k0 + tx;
            s[ty + 8 * i][tx] = (k < C_) ? wih[(size_t)row * C_ + k]
                                         : whh[(size_t)row * H_ + (k - C_)];
        }
        __syncthreads();
        #pragma unroll
        for (int i = 0; i < 4; i++) {
            int k = k0 + ty + 8 * i;
            g_Wt[(size_t)k * M_ + r0 + tx] = s[tx][ty + 8 * i];
        }
    } else {
        #pragma unroll
        for (int i = 0; i < 4; i++) {
            int row = r0 + ty + 8 * i, k = k0 + tx;
            s[ty + 8 * i][tx] = (row < HID_) ? w0h[(size_t)row * C_ + k]
                                             : w0c[(size_t)(row - HID_) * C_ + k];
        }
        __syncthreads();
        #pragma unroll
        for (int i = 0; i < 4; i++) {
            int k = k0 + ty + 8 * i;
            g_Wt0[(size_t)k * M_ + r0 + tx] = s[tx][ty + 8 * i];
        }
    }
}

// ------ x transpose to [t][b][s][c] + fused pooling into g_A0[k][b] --------
__global__ __launch_bounds__(256) void k_xt(const float* __restrict__ x) {
    __shared__ float sm[64][51];
    int c0 = blockIdx.x * 64;
    int t  = blockIdx.y;
    int b  = blockIdx.z;
    int w = threadIdx.x >> 5, lane = threadIdx.x & 31;
    #pragma unroll
    for (int rr = 0; rr < 8; rr++) {
        int cc = w * 8 + rr;
        int c  = c0 + cc;
        const float* src = x + (((size_t)(b * C_ + c) * T_) + t) * S_;
        float v1 = __ldcs(src + lane);
        float v2 = (lane < S_ - 32) ? __ldcs(src + 32 + lane) : 0.f;
        sm[cc][lane] = v1;
        if (lane < S_ - 32) sm[cc][32 + lane] = v2;
        float s = warp_sum(v1 + v2);
        if (lane == 0) atomicAdd(&g_A0[(size_t)c * B_ + b], s * (1.0f / 784.0f));
    }
    __syncthreads();
    size_t base = ((size_t)(t * B_ + b) * S_) * C_ + c0;
    for (int idx = threadIdx.x; idx < S_ * 16; idx += 256) {
        int s = idx >> 4, c4 = (idx & 15) * 4;
        float4 v = make_float4(sm[c4][s], sm[c4 + 1][s], sm[c4 + 2][s], sm[c4 + 3][s]);
        __stcs((float4*)(g_xt + base + (size_t)s * C_ + c4), v);
    }
}

// ------- split-K GEMM, pipelined W prefetch. grid 256 = 8 tiles x 32 splits -
// SEL=0: layer0 (KC=64); SEL=1: gates (KC=80). thread: 4 rows x 8 batches
template<int SEL>
__global__ __launch_bounds__(256) void k_gemm() {
    constexpr int KC  = SEL ? 80 : 64;
    constexpr int NCH = KC / 4;
    const float* __restrict__ Wt = SEL ? g_Wt : g_Wt0;
    const float* __restrict__ A  = SEL ? g_A  : g_A0;
    __shared__ float sA[80 * 32];
    int rt = blockIdx.x & 7;
    int ks = blockIdx.x >> 3;
    int k0 = ks * KC;
    for (int i = threadIdx.x; i < (KC * 32) / 4; i += 256)
        ((float4*)sA)[i] = ((const float4*)(A + (size_t)k0 * 32))[i];
    __syncthreads();

    int w = threadIdx.x >> 5, lane = threadIdx.x & 31;
    int r0 = rt * 256 + w * 32 + (lane >> 2) * 4;
    int b0 = (lane & 3) * 8;

    float acc[4][8];
    #pragma unroll
    for (int i = 0; i < 4; i++)
        #pragma unroll
        for (int j = 0; j < 8; j++) acc[i][j] = 0.f;

    const float* wp = Wt + (size_t)k0 * M_ + r0;
    const float* ap = sA + b0;

    float4 wb0[4], wb1[4];
    #pragma unroll
    for (int p = 0; p < 4; p++)
        wb0[p] = *(const float4*)(wp + (size_t)p * M_);

    #define FMA_BLOCK(WV, KK) do {                                           \
        float4 av0 = *(const float4*)(ap + (KK) * 32);                        \
        float4 av1 = *(const float4*)(ap + (KK) * 32 + 4);                    \
        float wf[4] = {(WV).x, (WV).y, (WV).z, (WV).w};                       \
        float af[8] = {av0.x, av0.y, av0.z, av0.w, av1.x, av1.y, av1.z, av1.w};\
        _Pragma("unroll")                                                     \
        for (int i = 0; i < 4; i++)                                           \
            _Pragma("unroll")                                                 \
            for (int j = 0; j < 8; j++)                                       \
                acc[i][j] = fmaf(wf[i], af[j], acc[i][j]);                    \
    } while (0)

    for (int ch = 0; ch < NCH; ch += 2) {
        if (ch + 1 < NCH) {
            const float* wn = wp + (size_t)(ch + 1) * 4 * M_;
            #pragma unroll
            for (int p = 0; p < 4; p++)
                wb1[p] = *(const float4*)(wn + (size_t)p * M_);
        }
        #pragma unroll
        for (int p = 0; p < 4; p++) FMA_BLOCK(wb0[p], ch * 4 + p);
        if (ch + 2 < NCH) {
            const float* wn = wp + (size_t)(ch + 2) * 4 * M_;
            #pragma unroll
            for (int p = 0; p < 4; p++)
                wb0[p] = *(const float4*)(wn + (size_t)p * M_);
        }
        if (ch + 1 < NCH) {
            #pragma unroll
            for (int p = 0; p < 4; p++) FMA_BLOCK(wb1[p], (ch + 1) * 4 + p);
        }
    }
    #undef FMA_BLOCK

    #pragma unroll
    for (int j = 0; j < 8; j++) {
        int b = b0 + j;
        float4 o = make_float4(acc[0][j], acc[1][j], acc[2][j], acc[3][j]);
        *(float4*)&g_part[((size_t)(ks * B_ + b) * M_) + r0] = o;
    }
}

// ---------------- layer0 reduce (32 splits) ---------------------------------
__global__ __launch_bounds__(256) void k_red0(
    const float* __restrict__ b_h, const float* __restrict__ b_c) {
    int gid = blockIdx.x * 256 + threadIdx.x;   // b*2048 + r
    int b = gid >> 11, r = gid & 2047;
    float s = 0.f;
    #pragma unroll 8
    for (int ks = 0; ks < 32; ks++) s += g_part[((size_t)(ks * B_ + b) * M_) + r];
    if (r < HID_) g_hidh[b * HID_ + r] = s + b_h[r];
    else          g_hidc[b * HID_ + (r - HID_)] = s + b_c[r - HID_];
}

// ---------------- layer1: 4 outputs per warp --------------------------------
__global__ __launch_bounds__(256) void k_layer1(
    const float* __restrict__ w_h, const float* __restrict__ b_h,
    const float* __restrict__ w_c, const float* __restrict__ b_c) {
    int gw   = (blockIdx.x * 256 + threadIdx.x) >> 5;
    int lane = threadIdx.x & 31;
    int path = gw >> 12;
    int r    = gw & 4095;
    int b    = r >> 7;
    int j0   = (r & 127) * 4;
    const float* w   = path ? w_c : w_h;
    const float* src = path ? g_hidc : g_hidh;
    const float4* sp = (const float4*)(src + b * HID_);
    const float4* w0 = (const float4*)(w + (size_t)(j0)     * HID_);
    const float4* w1 = (const float4*)(w + (size_t)(j0 + 1) * HID_);
    const float4* w2 = (const float4*)(w + (size_t)(j0 + 2) * HID_);
    const float4* w3 = (const float4*)(w + (size_t)(j0 + 3) * HID_);
    float a0 = 0.f, a1 = 0.f, a2 = 0.f, a3 = 0.f;
    #pragma unroll 2
    for (int i = lane; i < HID_ / 4; i += 32) {
        float4 s4 = sp[i];
        float4 v;
        v = w0[i]; a0 += s4.x * v.x + s4.y * v.y + s4.z * v.z + s4.w * v.w;
        v = w1[i]; a1 += s4.x * v.x + s4.y * v.y + s4.z * v.z + s4.w * v.w;
        v = w2[i]; a2 += s4.x * v.x + s4.y * v.y + s4.z * v.z + s4.w * v.w;
        v = w3[i]; a3 += s4.x * v.x + s4.y * v.y + s4.z * v.z + s4.w * v.w;
    }
    a0 = warp_sum(a0); a1 = warp_sum(a1); a2 = warp_sum(a2); a3 = warp_sum(a3);
    if (lane == 0) {
        float o[4] = {a0, a1, a2, a3};
        #pragma unroll
        for (int m = 0; m < 4; m++) {
            int j = j0 + m;
            float v = o[m] + (path ? b_c[j] : b_h[j]);
            if (path == 0) {
                g_h0[b * H_ + j] = v;
                g_A[(size_t)(C_ + j) * B_ + b] = v;
            } else {
                g_c[b * H_ + j] = v;
            }
        }
    }
}

// ---------------- initial alpha from h0 ------------------------------------
__global__ __launch_bounds__(256) void k_alpha_init(
    const float* __restrict__ att_w, float* __restrict__ alpha_out) {
    int b = blockIdx.x;
    __shared__ float sh_h[H_];
    __shared__ float sh_e[56];
    int tid = threadIdx.x, warp = tid >> 5, lane = tid & 31;
    for (int i = tid; i < H_; i += 256) sh_h[i] = g_h0[b * H_ + i];
    __syncthreads();
    for (int s = warp; s < S_; s += 8) {
        float acc = 0.f;
        #pragma unroll
        for (int i = 0; i < 16; i++)
            acc += sh_h[lane + 32 * i] * __ldg(att_w + (size_t)s * H_ + lane + 32 * i);
        acc = warp_sum(acc);
        if (lane == 0) sh_e[s] = acc;
    }
    __syncthreads();
    if (warp == 0) {
        float e1 = sh_e[lane];
        float e2 = (lane < 17) ? sh_e[lane + 32] : -1e30f;
        float m = fmaxf(e1, e2);
        #pragma unroll
        for (int o = 16; o; o >>= 1) m = fmaxf(m, __shfl_xor_sync(0xFFFFFFFFu, m, o));
        float p1 = expf(e1 - m);
        float p2 = (lane < 17) ? expf(e2 - m) : 0.f;
        float sum = warp_sum(p1 + p2);
        float inv = 1.0f / sum;
        p1 *= inv; p2 *= inv;
        g_alpha[b * 64 + lane] = p1;
        alpha_out[((size_t)b * T_) * S_ + lane] = p1;
        if (lane < 17) {
            g_alpha[b * 64 + 32 + lane] = p2;
            alpha_out[((size_t)b * T_) * S_ + 32 + lane] = p2;
        }
    }
}

// ---------------- per step: context from g_xt (coalesced, float2) ----------
__global__ __launch_bounds__(256) void k_ctx(int t) {
    int b = blockIdx.x >> 2;
    int q = blockIdx.x & 3;
    __shared__ float sal[S_];
    if (threadIdx.x < S_) sal[threadIdx.x] = g_alpha[b * 64 + threadIdx.x];
    __syncthreads();
    int c = q * 512 + threadIdx.x * 2;
    const float* base = g_xt + ((size_t)(t * B_ + b) * S_) * C_ + c;
    float ax = 0.f, ay = 0.f;
    #pragma unroll 7
    for (int s = 0; s < S_; s++) {
        float2 v = __ldcs((const float2*)(base + (size_t)s * C_));
        float a = sal[s];
        ax = fmaf(a, v.x, ax);
        ay = fmaf(a, v.y, ay);
    }
    g_A[(size_t)c * B_ + b]       = ax;
    g_A[(size_t)(c + 1) * B_ + b] = ay;
}

// -- per step: two-half reduce(32) + LSTM cell + next alpha (1024 threads) --
__global__ __launch_bounds__(1024) void k_cell(
    const float* __restrict__ b_ih, const float* __restrict__ b_hh,
    const float* __restrict__ att_w, float* __restrict__ alpha_out, int t) {
    int b = blockIdx.x;
    int tid = threadIdx.x;
    __shared__ float sgA[M_];      // splits 0..15 reduced
    __shared__ float sgB[M_];      // splits 16..31 reduced
    __shared__ float sh_h[H_];
    __shared__ float sh_e[56];

    // phase 1: half = tid>>9 handles 16 splits; float4 column per thread
    {
        int half = tid >> 9;           // 0 or 1
        int j4   = (tid & 511) * 4;    // [0, 2048)
        float4 acc = make_float4(0.f, 0.f, 0.f, 0.f);
        int s0 = half * 16;
        #pragma unroll
        for (int ks = 0; ks < 16; ks++) {
            float4 v = *(const float4*)&g_part[((size_t)((s0 + ks) * B_ + b) * M_) + j4];
            acc.x += v.x; acc.y += v.y; acc.z += v.z; acc.w += v.w;
        }
        *(float4*)&(half ? sgB : sgA)[j4] = acc;
    }
    __syncthreads();

    // phase 2: threads 0..511 do per-row cell math
    if (tid < 512) {
        int j = tid;
        float gi = sgA[j]        + sgB[j]        + b_ih[j]        + b_hh[j];
        float gf = sgA[512 + j]  + sgB[512 + j]  + b_ih[512 + j]  + b_hh[512 + j];
        float gg = sgA[1024 + j] + sgB[1024 + j] + b_ih[1024 + j] + b_hh[1024 + j];
        float go = sgA[1536 + j] + sgB[1536 + j] + b_ih[1536 + j] + b_hh[1536 + j];

        float iv = sigmoidf_(gi);
        float fv = sigmoidf_(gf);
        float gv = tanhf(gg);
        float ov = sigmoidf_(go);
        int idx = b * H_ + j;
        float cn = fv * g_c[idx] + iv * gv;
        g_c[idx] = cn;
        float hn = ov * tanhf(cn);
        g_A[(size_t)(C_ + j) * B_ + b] = hn;
        g_hsum[idx] = (t == 0) ? hn : (g_hsum[idx] + hn);
        sh_h[j] = hn;
    }
    __syncthreads();

    if (t < T_ - 1) {
        int warp = tid >> 5, lane = tid & 31;
        for (int s = warp; s < S_; s += 32) {
            float acc = 0.f;
            #pragma unroll
            for (int i = 0; i < 16; i++)
                acc += sh_h[lane + 32 * i] * __ldg(att_w + (size_t)s * H_ + lane + 32 * i);
            acc = warp_sum(acc);
            if (lane == 0) sh_e[s] = acc;
        }
        __syncthreads();
        if (warp == 0) {
            float e1 = sh_e[lane];
            float e2 = (lane < 17) ? sh_e[lane + 32] : -1e30f;
            float m = fmaxf(e1, e2);
            #pragma unroll
            for (int o = 16; o; o >>= 1) m = fmaxf(m, __shfl_xor_sync(0xFFFFFFFFu, m, o));
            float p1 = expf(e1 - m);
            float p2 = (lane < 17) ? expf(e2 - m) : 0.f;
            float sum = warp_sum(p1 + p2);
            float inv = 1.0f / sum;
            p1 *= inv; p2 *= inv;
            g_alpha[b * 64 + lane] = p1;
            alpha_out[((size_t)b * T_ + (t + 1)) * S_ + lane] = p1;
            if (lane < 17) {
                g_alpha[b * 64 + 32 + lane] = p2;
                alpha_out[((size_t)b * T_ + (t + 1)) * S_ + 32 + lane] = p2;
            }
        }
    }
}

// ---------------- final output GEMV ----------------------------------------
__global__ __launch_bounds__(256) void k_final(
    const float* __restrict__ fc_out_w, const float* __restrict__ fc_out_b,
    float* __restrict__ out) {
    int gwid = (blockIdx.x * blockDim.x + threadIdx.x) >> 5;
    int lane = threadIdx.x & 31;
    if (gwid >= B_ * OUT_) return;
    int b = gwid / OUT_;
    int o = gwid % OUT_;
    const float4* wp = (const float4*)(fc_out_w + (size_t)o * H_);
    const float4* hp = (const float4*)(g_hsum + b * H_);
    float acc = 0.f;
    #pragma unroll 4
    for (int i = lane; i < H_ / 4; i += 32) {
        float4 a = hp[i], w = wp[i];
        acc += a.x * w.x + a.y * w.y + a.z * w.z + a.w * w.w;
    }
    acc = warp_sum(acc);
    if (lane == 0) out[gwid] = acc * (1.0f / (float)T_) + fc_out_b[o];
}

// ---------------- launch ----------------------------------------------------
extern "C" void kernel_launch(void* const* d_in, const int* in_sizes, int n_in,
                              void* d_out, int out_size) {
    const float* input_x   = (const float*)d_in[0];
    const float* att_hw_w  = (const float*)d_in[1];
    const float* fc_h0_0_w = (const float*)d_in[2];
    const float* fc_h0_0_b = (const float*)d_in[3];
    const float* fc_h0_1_w = (const float*)d_in[4];
    const float* fc_h0_1_b = (const float*)d_in[5];
    const float* fc_c0_0_w = (const float*)d_in[6];
    const float* fc_c0_0_b = (const float*)d_in[7];
    const float* fc_c0_1_w = (const float*)d_in[8];
    const float* fc_c0_1_b = (const float*)d_in[9];
    const float* w_ih      = (const float*)d_in[10];
    const float* b_ih      = (const float*)d_in[11];
    const float* w_hh      = (const float*)d_in[12];
    const float* b_hh      = (const float*)d_in[13];
    const float* fc_out_w  = (const float*)d_in[14];
    const float* fc_out_b  = (const float*)d_in[15];

    float* out       = (float*)d_out;
    float* alpha_out = out + B_ * OUT_;

    k_tw<<<dim3(KTOT_ / 32, M_ / 32, 2), 256>>>(w_ih, w_hh, fc_h0_0_w, fc_c0_0_w);
    k_xt<<<dim3(C_ / 64, T_, B_), 256>>>(input_x);      // transpose + fused pooling
    k_gemm<0><<<256, 256>>>();                          // layer0 GEMM (32 splits)
    k_red0<<<(B_ * M_) / 256, 256>>>(fc_h0_0_b, fc_c0_0_b);
    k_layer1<<<1024, 256>>>(fc_h0_1_w, fc_h0_1_b, fc_c0_1_w, fc_c0_1_b);
    k_alpha_init<<<B_, 256>>>(att_hw_w, alpha_out);

    for (int t = 0; t < T_; t++) {
        k_ctx<<<B_ * 4, 256>>>(t);
        k_gemm<1><<<256, 256>>>();                      // gates GEMM (32 splits)
        k_cell<<<B_, 1024>>>(b_ih, b_hh, att_hw_w, alpha_out, t);
    }

    k_final<<<(B_ * OUT_ + 7) / 8, 256>>>(fc_out_w, fc_out_b, out);
}